// round 6
// baseline (speedup 1.0000x reference)
#include <cuda_runtime.h>
#include <cuda_bf16.h>
#include <math.h>
#include <float.h>
#include <stdint.h>

#define BATCH 2
#define NCTX  2048
#define DIM   512
#define HEADS 8
#define DHEAD 64
#define KNN   32
#define MDB   131072
#define MROWS (BATCH*NCTX)   // 4096
#define KS    1024           // bf16 storage: [hi(512) | lo(512)]
#define NCH   24             // logical K' = 1536 = 24 chunks of 64

// scratch (device globals; no allocation allowed)
__device__ float g_q[MROWS * DIM];
__device__ float g_o[MROWS * DIM];
__device__ __nv_bfloat16 g_a2[(size_t)MROWS * KS];  // 8 MB
__device__ __nv_bfloat16 g_b2[(size_t)DIM * KS];    // 1 MB

__device__ __forceinline__ uint32_t smem_u32(const void* p) {
    uint32_t a;
    asm("{ .reg .u64 t; cvta.to.shared.u64 t, %1; cvt.u32.u64 %0, t; }" : "=r"(a) : "l"(p));
    return a;
}
#define SW128(x) ((x) ^ (((x) >> 3) & 0x70))

#define LDSM_X4(r0, r1, r2, r3, addr) \
    asm volatile("ldmatrix.sync.aligned.m8n8.x4.shared.b16 {%0,%1,%2,%3}, [%4];" \
        : "=r"(r0), "=r"(r1), "=r"(r2), "=r"(r3) : "r"(addr))

#define MMA16816(c, a, b0, b1) \
    asm volatile("mma.sync.aligned.m16n8k16.row.col.f32.bf16.bf16.f32 " \
        "{%0,%1,%2,%3}, {%4,%5,%6,%7}, {%8,%9}, {%0,%1,%2,%3};" \
        : "+f"((c)[0]), "+f"((c)[1]), "+f"((c)[2]), "+f"((c)[3]) \
        : "r"((a)[0]), "r"((a)[1]), "r"((a)[2]), "r"((a)[3]), "r"(b0), "r"(b1))

// ---------------------------------------------------------------------------
// split: fp32 [rows, 512] -> bf16 [rows, 1024] = [hi | lo]
// ---------------------------------------------------------------------------
__global__ void split2(const float* __restrict__ in, __nv_bfloat16* __restrict__ out,
                       int rows)
{
    int idx = blockIdx.x * blockDim.x + threadIdx.x;
    if (idx >= rows * (DIM / 4)) return;
    int r  = idx / (DIM / 4);
    int c4 = (idx % (DIM / 4)) * 4;
    float4 v = *(const float4*)(in + (long)r * DIM + c4);

    float vv[4] = {v.x, v.y, v.z, v.w};
    unsigned long long hp = 0, lp = 0;
#pragma unroll
    for (int i = 0; i < 4; i++) {
        __nv_bfloat16 h = __float2bfloat16(vv[i]);
        __nv_bfloat16 l = __float2bfloat16(vv[i] - __bfloat162float(h));
        hp |= (unsigned long long)__bfloat16_as_ushort(h) << (16 * i);
        lp |= (unsigned long long)__bfloat16_as_ushort(l) << (16 * i);
    }
    __nv_bfloat16* base = out + (long)r * KS + c4;
    *(unsigned long long*)(base)       = hp;
    *(unsigned long long*)(base + 512) = lp;
}

// ---------------------------------------------------------------------------
// bf16 mma.sync GEMM: C = A*B^T with emulated-fp32 3-term schedule.
// Logical K' = 1536; chunk c sources: A block (c<8 ? c : c-8), B block
// (c<16 ? c : c-16) from [hi|lo] storage of width KS=1024.
// CTA 128x128, 8 warps (2x4), warp 64x32, BK=64, double-buffered smem.
// ---------------------------------------------------------------------------
#define TILEB (128 * 128)
#define SO_A0 0
#define SO_A1 TILEB
#define SO_B0 (2 * TILEB)
#define SO_B1 (3 * TILEB)
#define GSMEM (4 * TILEB)         // 64 KB

__device__ __forceinline__ int a_src(int c) { return (c < 8) ? c : c - 8; }
__device__ __forceinline__ int b_src(int c) { return (c < 16) ? c : c - 16; }

__global__ void __launch_bounds__(256, 1) gemm_mma(
    const __nv_bfloat16* __restrict__ A,
    const __nv_bfloat16* __restrict__ B,
    float* __restrict__ C, int N)
{
    extern __shared__ char smem[];
    uint32_t sb = smem_u32(smem);
    const int tid  = threadIdx.x;
    const int wid  = tid >> 5, lane = tid & 31;
    const int wr   = wid >> 2;
    const int wc   = wid & 3;
    const int row0 = blockIdx.y * 128, col0 = blockIdx.x * 128;

    const int sr = tid >> 3;
    const int sc = (tid & 7) * 16;

    const uint32_t a_l = (uint32_t)((lane & 15) * 128 + ((lane >> 4) & 1) * 16);
    const uint32_t b_l = (uint32_t)(((lane & 7) + ((lane >> 4) & 1) * 8) * 128 + ((lane >> 3) & 1) * 16);

    const uint32_t aoff[2] = {SO_A0, SO_A1}, boff[2] = {SO_B0, SO_B1};

    float acc[4][4][4];
#pragma unroll
    for (int i = 0; i < 4; i++)
#pragma unroll
        for (int j = 0; j < 4; j++)
#pragma unroll
            for (int k = 0; k < 4; k++) acc[i][j][k] = 0.f;

    uint4 va[4], vb[4];
#pragma unroll
    for (int i = 0; i < 4; i++) {
        int r = sr + i * 32;
        va[i] = *(const uint4*)(A + (long)(row0 + r) * KS + (sc >> 1));
        vb[i] = *(const uint4*)(B + (long)(col0 + r) * KS + (sc >> 1));
    }
#pragma unroll
    for (int i = 0; i < 4; i++) {
        int r = sr + i * 32;
        *(uint4*)(smem + SO_A0 + SW128(r * 128 + sc)) = va[i];
        *(uint4*)(smem + SO_B0 + SW128(r * 128 + sc)) = vb[i];
    }
    __syncthreads();

    for (int c = 0; c < NCH; c++) {
        int buf = c & 1;
        if (c + 1 < NCH) {
            int ka = a_src(c + 1) * 64, kb = b_src(c + 1) * 64;
#pragma unroll
            for (int i = 0; i < 4; i++) {
                int r = sr + i * 32;
                va[i] = *(const uint4*)(A + (long)(row0 + r) * KS + ka + (sc >> 1));
                vb[i] = *(const uint4*)(B + (long)(col0 + r) * KS + kb + (sc >> 1));
            }
        }

        uint32_t sa  = sb + aoff[buf] + wr * (64 * 128);
        uint32_t sbm = sb + boff[buf] + wc * (32 * 128);

#pragma unroll
        for (int ks = 0; ks < 4; ks++) {
            uint32_t bf[8];
#pragma unroll
            for (int np = 0; np < 2; np++) {
                uint32_t x = b_l + np * 2048 + ks * 32;
                LDSM_X4(bf[np * 4 + 0], bf[np * 4 + 1], bf[np * 4 + 2], bf[np * 4 + 3],
                        sbm + SW128(x));
            }
#pragma unroll
            for (int mt = 0; mt < 4; mt++) {
                uint32_t af[4];
                uint32_t x = a_l + mt * 2048 + ks * 32;
                LDSM_X4(af[0], af[1], af[2], af[3], sa + SW128(x));
#pragma unroll
                for (int nt = 0; nt < 4; nt++)
                    MMA16816(acc[mt][nt], af, bf[nt * 2], bf[nt * 2 + 1]);
            }
        }

        if (c + 1 < NCH) {
            int nb = (c + 1) & 1;
#pragma unroll
            for (int i = 0; i < 4; i++) {
                int r = sr + i * 32;
                *(uint4*)(smem + aoff[nb] + SW128(r * 128 + sc)) = va[i];
                *(uint4*)(smem + boff[nb] + SW128(r * 128 + sc)) = vb[i];
            }
        }
        __syncthreads();
    }

    const int qr = lane >> 2, qc = (lane & 3) * 2;
#pragma unroll
    for (int mt = 0; mt < 4; mt++) {
#pragma unroll
        for (int nt = 0; nt < 4; nt++) {
            int r = row0 + wr * 64 + mt * 16 + qr;
            int cc = col0 + wc * 32 + nt * 8 + qc;
            *(float2*)(C + (long)r * N + cc)       = make_float2(acc[mt][nt][0], acc[mt][nt][1]);
            *(float2*)(C + (long)(r + 8) * N + cc) = make_float2(acc[mt][nt][2], acc[mt][nt][3]);
        }
    }
}

// ---------------------------------------------------------------------------
// KNN attention v2: one warp per query; smem-staged, shuffle-free core.
// Per-warp region: kv rows (32 x 68 floats), q (64), attn (32), idx (32), msk (32).
// ---------------------------------------------------------------------------
#define AW     8                       // warps per CTA
#define RSTR   68                      // kv row stride in floats (conflict-free)
#define WBUF   (32 * RSTR + 64 + 32 + 32 + 32)   // 2336 floats = 9344 B
#define ASMEM  (AW * WBUF * 4)         // 74752 B

__global__ void __launch_bounds__(256) knn_attn2(
    const float* __restrict__ mem_db,
    const int*   __restrict__ knn_idx,
    const int*   __restrict__ mem_mask,
    const float* __restrict__ scale_param)
{
    extern __shared__ float sm[];
    const unsigned FULL = 0xffffffffu;
    const int tid = threadIdx.x, lane = tid & 31, w = tid >> 5;

    float* wb   = sm + w * WBUF;
    float* kvb  = wb;                  // 32 x 68
    float* qsm  = wb + 32 * RSTR;      // 64
    float* atsm = qsm + 64;            // 32
    int*   idxs = (int*)(atsm + 32);   // 32
    int*   msks = idxs + 32;           // 32

    const int warp = blockIdx.x * AW + w;        // 0..65535
    const int n  = warp & (NCTX - 1);
    const int bh = warp >> 11;
    const int h  = bh & (HEADS - 1);
    const int b  = bh >> 3;

    // q load + normalize (5 shfl) + stage
    const float* qp = g_q + ((long)(b * NCTX + n) * DIM) + h * DHEAD;
    float q0 = qp[lane], q1 = qp[lane + 32];
    float ss = q0 * q0 + q1 * q1;
#pragma unroll
    for (int o = 16; o > 0; o >>= 1) ss += __shfl_xor_sync(FULL, ss, o);
    float inv = expf(scale_param[h]) / fmaxf(sqrtf(ss), 1e-12f);
    qsm[lane]      = q0 * inv;
    qsm[lane + 32] = q1 * inv;

    long ib = (long)((b * HEADS + h) * NCTX + n) * KNN;
    idxs[lane] = knn_idx[ib + lane];
    msks[lane] = mem_mask[ib + lane];
    __syncwarp();

    const float* db = mem_db + (long)b * MDB * 128;
    const int rowp = lane >> 4;        // 0/1
    const int c16  = lane & 15;        // float4 slot in 64-float row

    // stage k rows (coalesced LDG.128 -> STS.128)
    float4 kr4[16];
#pragma unroll
    for (int i = 0; i < 16; i++) {
        int row = 2 * i + rowp;
        long ij = idxs[row];
        kr4[i] = *(const float4*)(db + ij * 128 + c16 * 4);
    }
#pragma unroll
    for (int i = 0; i < 16; i++) {
        int row = 2 * i + rowp;
        *(float4*)(kvb + row * RSTR + c16 * 4) = kr4[i];
    }
    __syncwarp();

    // issue v loads early (overlap with sim compute)
    float4 vr4[16];
#pragma unroll
    for (int i = 0; i < 16; i++) {
        int row = 2 * i + rowp;
        long ij = idxs[row];
        vr4[i] = *(const float4*)(db + ij * 128 + 64 + c16 * 4);
    }

    // sim_j on lane j: dot(q, k_j) from smem, zero shuffles
    float sim = 0.f;
    const float* kr = kvb + lane * RSTR;
#pragma unroll
    for (int d = 0; d < 16; d++) {
        float4 qv = *(const float4*)(qsm + d * 4);
        float4 k4 = *(const float4*)(kr + d * 4);
        sim = fmaf(qv.x, k4.x, fmaf(qv.y, k4.y, fmaf(qv.z, k4.z, fmaf(qv.w, k4.w, sim))));
    }
    if (!msks[lane]) sim = -FLT_MAX;

    // softmax over lanes (10 shfl)
    float m = sim;
#pragma unroll
    for (int o = 16; o > 0; o >>= 1) m = fmaxf(m, __shfl_xor_sync(FULL, m, o));
    float p = __expf(sim - m);
    float s = p;
#pragma unroll
    for (int o = 16; o > 0; o >>= 1) s += __shfl_xor_sync(FULL, s, o);
    atsm[lane] = p / s;
    __syncwarp();                      // kvb sim-reads done; attn visible

    // stage v rows into the same buffer
#pragma unroll
    for (int i = 0; i < 16; i++) {
        int row = 2 * i + rowp;
        *(float4*)(kvb + row * RSTR + c16 * 4) = vr4[i];
    }
    __syncwarp();

    // out dims (2*lane, 2*lane+1) = sum_j attn_j * v_j[2l..]
    float o0 = 0.f, o1 = 0.f;
#pragma unroll
    for (int j = 0; j < 32; j++) {
        float a   = atsm[j];
        float2 v2 = *(const float2*)(kvb + j * RSTR + lane * 2);
        o0 = fmaf(a, v2.x, o0);
        o1 = fmaf(a, v2.y, o1);
    }

    float* op = g_o + ((long)(b * NCTX + n) * DIM) + h * DHEAD;
    *(float2*)(op + lane * 2) = make_float2(o0, o1);
}

// ---------------------------------------------------------------------------
extern "C" void kernel_launch(void* const* d_in, const int* in_sizes, int n_in,
                              void* d_out, int out_size)
{
    const float* x        = (const float*)d_in[0];
    const float* mem_db   = (const float*)d_in[1];
    const int*   knn_idx  = (const int*)d_in[2];
    const int*   mem_mask = (const int*)d_in[3];
    const float* Wq       = (const float*)d_in[4];
    // d_in[5] = Wkv : dead code in the reference, never used
    const float* Wout     = (const float*)d_in[6];
    const float* scale_p  = (const float*)d_in[7];
    float* out = (float*)d_out;

    float *qb, *ob;
    __nv_bfloat16 *a2, *b2;
    cudaGetSymbolAddress((void**)&qb, g_q);
    cudaGetSymbolAddress((void**)&ob, g_o);
    cudaGetSymbolAddress((void**)&a2, g_a2);
    cudaGetSymbolAddress((void**)&b2, g_b2);

    cudaFuncSetAttribute(gemm_mma,  cudaFuncAttributeMaxDynamicSharedMemorySize, GSMEM);
    cudaFuncSetAttribute(knn_attn2, cudaFuncAttributeMaxDynamicSharedMemorySize, ASMEM);

    dim3 gGemm(DIM / 128, MROWS / 128);   // (4, 32) = 128 CTAs
    const int splitA_blocks = (MROWS * (DIM / 4) + 255) / 256;  // 2048
    const int splitB_blocks = (DIM   * (DIM / 4) + 255) / 256;  // 256

    // 1) q = x @ Wq^T  (bf16x3 emulated-fp32 tensor-core GEMM)
    split2<<<splitA_blocks, 256>>>(x, a2, MROWS);
    split2<<<splitB_blocks, 256>>>(Wq, b2, DIM);
    gemm_mma<<<gGemm, 256, GSMEM>>>(a2, b2, qb, DIM);

    // 2) gather-attention (smem-staged, shuffle-free core)
    int nwarps = BATCH * HEADS * NCTX;            // 65536
    knn_attn2<<<nwarps / AW, 32 * AW, ASMEM>>>(mem_db, knn_idx, mem_mask, scale_p);

    // 3) out = attn_out @ Wout^T
    split2<<<splitA_blocks, 256>>>(ob, a2, MROWS);
    split2<<<splitB_blocks, 256>>>(Wout, b2, DIM);
    gemm_mma<<<gGemm, 256, GSMEM>>>(a2, b2, out, DIM);
}